// round 16
// baseline (speedup 1.0000x reference)
#include <cuda_runtime.h>
#include <cuda_bf16.h>
#include <cuda_fp16.h>
#include <math.h>

#define BATCH 128
#define HW 224
#define CH 3
#define KK 32
#define PAD_LO 15                       // SAME pad for K=32: lo=15, hi=16
#define ROW_FLOATS (HW * CH)            // 672
#define ELEMS_PER_IMG (HW * HW * CH)    // 150528
#define MAX_TAPS 64

#define RB 32                           // output rows per block
#define XB 56                           // output cols per block
#define SROWS (RB + 31)                 // staged rows = 63
#define SPPX (XB + 32)                  // staged row width = 88 px
#define STOT (SROWS * SPPX)             // 5544 staged px
#define NTHREADS 448                    // 8 row-groups x 56 px; 14 warps
#define NWARPS (NTHREADS / 32)

__device__ int   g_cnt[BATCH];
__device__ float g_w[BATCH];            // uniform nonzero weight = 1/size
__device__ int   g_off[BATCH][MAX_TAPS];  // tap offset: dy*SPPX + dx (px units)

__device__ __forceinline__ __half2 u32_to_h2(unsigned u) {
    union { unsigned u; __half2 h; } cv; cv.u = u; return cv.h;
}

// ---------------------------------------------------------------------------
// Kernel 1: build rotated sparse tap list. One block per sample, one thread
// per kernel cell. Compaction order irrelevant (all nonzero weights equal).
// ---------------------------------------------------------------------------
__global__ void build_taps_kernel(const float* __restrict__ tbl,
                                  const int* __restrict__ amt,
                                  const int* __restrict__ angles) {
    const int b = blockIdx.x;
    const int tid = threadIdx.x;           // 0..1023
    const int yy = tid >> 5;
    const int xx = tid & 31;

    __shared__ int s_cnt;
    if (tid == 0) s_cnt = 0;
    __syncthreads();

    float rad = (float)angles[b] * 0.017453292519943295f;
    float c = cosf(rad);
    float s = sinf(rad);
    const float e = 31.0f;
    float x_off = (e - (c * e - s * e)) * 0.5f;
    float y_off = (e - (s * e + c * e)) * 0.5f;

    float sx = c * (float)xx - s * (float)yy + x_off;
    float sy = s * (float)xx + c * (float)yy + y_off;
    int ix = __float2int_rn(sx);           // round half to even == jnp.round
    int iy = __float2int_rn(sy);

    if (ix >= 0 && ix < KK && iy >= 0 && iy < KK) {
        // reference indexes kernels_table[amt] directly
        float w = tbl[((size_t)amt[b] * (KK * KK) + iy * KK + ix) * CH];
        if (w != 0.0f) {
            int dy = yy - PAD_LO;
            int dx = xx - PAD_LO;
            int k = atomicAdd(&s_cnt, 1);
            g_off[b][k] = dy * SPPX + dx;  // px-unit offset in staged tile
            g_w[b] = w;                    // all equal; benign race
        }
    }
    __syncthreads();
    if (tid == 0) g_cnt[b] = s_cnt;
}

// ---------------------------------------------------------------------------
// Kernel 2 (fused): zero-fill tile, float4 warp-per-row staging into
// fp16-RGBX tile, then sparse conv from SMEM.
// Block = 32 rows x 56 cols; thread = 1 px x 4 rows (rg, rg+8, rg+16, rg+24).
// 4 blocks co-resident per SM.
// ---------------------------------------------------------------------------
__global__ void __launch_bounds__(NTHREADS, 4)
blur_fused_kernel(const float* __restrict__ in, float* __restrict__ out) {
    extern __shared__ char sm[];
    int*    s_off = (int*)sm;                      // 256 B
    uint2*  tile  = (uint2*)(sm + 256);            // STOT*8 = 44352 B
    __half* tileh = (__half*)tile;

    const int xb  = blockIdx.x * XB;
    const int yb  = blockIdx.y * RB;
    const int b   = blockIdx.z;
    const int tid = threadIdx.x;
    const int cnt = g_cnt[b];

    if (tid < cnt) s_off[tid] = g_off[b][tid];

    // ---- zero-fill tile (covers halos + w-lanes) ----
    {
        uint4  z  = make_uint4(0u, 0u, 0u, 0u);
        uint4* t4 = (uint4*)tile;
        #pragma unroll
        for (int i = tid; i < STOT / 2; i += NTHREADS) t4[i] = z;
    }
    __syncthreads();

    // ---- stage: warp-per-row, float4 coalesced loads ----
    // Valid source span per row is block-uniform and float4-aligned.
    const float* img = in + (size_t)b * ELEMS_PER_IMG;
    {
        const int warp = tid >> 5;
        const int lane = tid & 31;
        const int xs_lo = (xb - 16 > 0) ? xb - 16 : 0;
        const int xs_hi = (xb + XB + 16 < HW) ? xb + XB + 16 : HW;
        const int n4    = ((xs_hi - xs_lo) * 3) >> 2;    // 54 or 66
        const int tpx0  = xs_lo - xb + 16;               // 0 or 16

        for (int r = warp; r < SROWS; r += NWARPS) {
            int ys = yb + r - 15;
            if ((unsigned)ys < (unsigned)HW) {
                const float4* src = (const float4*)(img + ys * ROW_FLOATS + xs_lo * CH);
                __half* hb = tileh + (size_t)(r * SPPX + tpx0) * 4;
                for (int j = lane; j < n4; j += 32) {
                    float4 v = __ldg(src + j);
                    int d3 = j / 3;                      // mul-hi
                    int m  = j - 3 * d3;                 // j % 3
                    int b0 = (j + d3) * 4;               // base half slot (px_rel*4)
                    int t1 = m + 1, t2 = m + 2;
                    hb[b0 + m]                    = __float2half_rn(v.x);
                    hb[b0 + t1 + (t1 >= 3)]       = __float2half_rn(v.y);
                    hb[b0 + t2 + (t2 >= 3)]       = __float2half_rn(v.z);
                    hb[b0 + m + 4]                = __float2half_rn(v.w);  // t3=m+3 -> +1 always
                }
            }
        }
    }
    __syncthreads();

    // ---- conv: thread = px x_local, rows yb+rg+{0,8,16,24} ----
    const int rg = tid / XB;               // 0..7
    const int xl = tid - rg * XB;          // 0..55

    const uint2* tp = tile + (15 + rg) * SPPX + (16 + xl);

    float a0 = 0.f, a1 = 0.f, a2 = 0.f;
    float b0 = 0.f, b1 = 0.f, b2 = 0.f;
    float c0 = 0.f, c1 = 0.f, c2 = 0.f;
    float d0 = 0.f, d1 = 0.f, d2 = 0.f;
    #pragma unroll 2
    for (int i = 0; i < cnt; i++) {
        int off = s_off[i];
        uint2 v0 = tp[off];
        uint2 v1 = tp[off +  8 * SPPX];
        uint2 v2 = tp[off + 16 * SPPX];
        uint2 v3 = tp[off + 24 * SPPX];
        float2 f0 = __half22float2(u32_to_h2(v0.x));
        float2 f1 = __half22float2(u32_to_h2(v1.x));
        float2 f2 = __half22float2(u32_to_h2(v2.x));
        float2 f3 = __half22float2(u32_to_h2(v3.x));
        a0 += f0.x; a1 += f0.y; a2 += __half2float(__low2half(u32_to_h2(v0.y)));
        b0 += f1.x; b1 += f1.y; b2 += __half2float(__low2half(u32_to_h2(v1.y)));
        c0 += f2.x; c1 += f2.y; c2 += __half2float(__low2half(u32_to_h2(v2.y)));
        d0 += f3.x; d1 += f3.y; d2 += __half2float(__low2half(u32_to_h2(v3.y)));
    }

    const float w = g_w[b];
    float* o = out + (size_t)b * ELEMS_PER_IMG
             + (size_t)(yb + rg) * ROW_FLOATS + (xb + xl) * CH;
    o[0] = w * a0;  o[1] = w * a1;  o[2] = w * a2;
    o += 8 * ROW_FLOATS;
    o[0] = w * b0;  o[1] = w * b1;  o[2] = w * b2;
    o += 8 * ROW_FLOATS;
    o[0] = w * c0;  o[1] = w * c1;  o[2] = w * c2;
    o += 8 * ROW_FLOATS;
    o[0] = w * d0;  o[1] = w * d1;  o[2] = w * d2;
}

// ---------------------------------------------------------------------------
// Inputs (metadata order): x f32[128,224,224,3], kernels_table f32[32,32,32,3],
//                          amt i32[128], angles i32[128]
// ---------------------------------------------------------------------------
extern "C" void kernel_launch(void* const* d_in, const int* in_sizes, int n_in,
                              void* d_out, int out_size) {
    const float* x      = (const float*)d_in[0];
    const float* tbl    = (const float*)d_in[1];
    const int*   amt    = (const int*)d_in[2];
    const int*   angles = (const int*)d_in[3];
    float*       out    = (float*)d_out;

    static int smem_set = 0;
    const int smem_bytes = 256 + STOT * 8;         // 44608
    if (!smem_set) {
        cudaFuncSetAttribute(blur_fused_kernel,
                             cudaFuncAttributeMaxDynamicSharedMemorySize, smem_bytes);
        smem_set = 1;
    }

    build_taps_kernel<<<BATCH, KK * KK>>>(tbl, amt, angles);

    dim3 cgrid(HW / XB, HW / RB, BATCH);   // 4 x 7 x 128
    blur_fused_kernel<<<cgrid, NTHREADS, smem_bytes>>>(x, out);
}